// round 1
// baseline (speedup 1.0000x reference)
#include <cuda_runtime.h>
#include <cuda_bf16.h>
#include <cstdint>

// ---------------- problem constants ----------------
#define BS   32
#define C    64
#define H    96
#define W    96
#define HW   (H*W)            // 9216
#define CHW  (C*HW)           // 589824
#define TT   64               // num types
#define HID  128              // 2c
#define EPS  1e-5f

// conv tiling
#define TILE_X 32
#define TILE_Y 8
#define TROWS  (TILE_Y+2)     // 10
#define TCOLS  (TILE_X+2)     // 34
#define TILE_ELEMS (C*TROWS*TCOLS)   // 21760
#define WK_ELEMS   (C*C)             // 4096
#define WSUM_ELEMS (8*C)             // 512
#define CONV_SMEM_FLOATS (TILE_ELEMS + WK_ELEMS + WSUM_ELEMS)
#define CONV_SMEM_BYTES  (CONV_SMEM_FLOATS*4)   // 105472

#define NTILES_X (W/TILE_X)   // 3
#define NTILES_Y (H/TILE_Y)   // 12
#define NTILES   (NTILES_X*NTILES_Y) // 36

// tail smem
#define TAIL_SMEM_BYTES ((2048+4096+2048+4096+32+32+64+32+16)*4)

// ---------------- device scratch (static: no runtime allocs allowed) ----
__device__ float g_f1[BS*CHW];                 // intermediate feature map (~75.5MB)
__device__ float g_wf1[9*C*C];                 // folded conv1 weights [k][ic][oc]
__device__ float g_wf2[9*C*C];
__device__ float g_bias1[C];
__device__ float g_bias2[C];
__device__ float g_part[BS*NTILES*C];          // pooled partial sums per tile

// ---------------- prep: fold BN into weights, layout [k][ic][oc] --------
__global__ void prep_kernel(const float* __restrict__ w1, const float* __restrict__ g1,
                            const float* __restrict__ b1, const float* __restrict__ m1,
                            const float* __restrict__ v1,
                            const float* __restrict__ w2, const float* __restrict__ g2,
                            const float* __restrict__ b2, const float* __restrict__ m2,
                            const float* __restrict__ v2) {
    int idx = blockIdx.x*256 + threadIdx.x;
    if (idx < 9*C*C) {
        int oc = idx & 63;
        int ic = (idx >> 6) & 63;
        int k  = idx >> 12;
        float s1 = g1[oc] * rsqrtf(v1[oc] + EPS);
        float s2 = g2[oc] * rsqrtf(v2[oc] + EPS);
        // source layout: w[oc][ic][ky][kx]
        g_wf1[idx] = w1[(oc*C + ic)*9 + k] * s1;
        g_wf2[idx] = w2[(oc*C + ic)*9 + k] * s2;
    }
    if (idx < C) {
        g_bias1[idx] = b1[idx] - m1[idx]*g1[idx]*rsqrtf(v1[idx] + EPS);
        g_bias2[idx] = b2[idx] - m2[idx]*g2[idx]*rsqrtf(v2[idx] + EPS);
    }
}

// ---------------- direct conv, 1 pixel/thread, 64 oc in 32 f32x2 accs ---
// STORE=1: read param input, write relu result to g_f1
// STORE=0: read g_f1, reduce relu result spatially into g_part
template<int STORE>
__launch_bounds__(256)
__global__ void conv_kernel(const float* __restrict__ xin) {
    extern __shared__ float smem[];
    float* tile = smem;                       // [C][TROWS][TCOLS]
    float* wk   = smem + TILE_ELEMS;          // [ic][oc] for current k
    float* wsum = wk + WK_ELEMS;              // [8 warps][C]

    const int tid = threadIdx.x;
    const int lx = tid & 31, ly = tid >> 5;
    const int x0 = blockIdx.x * TILE_X, y0 = blockIdx.y * TILE_Y;
    const int b  = blockIdx.z;

    const float* in   = STORE ? xin : g_f1;
    const float* wf   = STORE ? g_wf1 : g_wf2;
    const float* bias = STORE ? g_bias1 : g_bias2;
    const float* inb  = in + (size_t)b * CHW;

    // load input tile with halo (zero pad at borders)
    for (int idx = tid; idx < TILE_ELEMS; idx += 256) {
        int col = idx % TCOLS;
        int t2  = idx / TCOLS;
        int row = t2 % TROWS;
        int ch  = t2 / TROWS;
        int gy = y0 + row - 1, gx = x0 + col - 1;
        float v = 0.f;
        if (gy >= 0 && gy < H && gx >= 0 && gx < W)
            v = inb[ch*HW + gy*W + gx];
        tile[idx] = v;
    }

    unsigned long long acc[32];   // acc[p] = f32x2 for oc (2p, 2p+1)
#pragma unroll
    for (int p = 0; p < 32; p++) acc[p] = 0ull;

    for (int k = 0; k < 9; k++) {
        __syncthreads();   // (k=0: tile ready; k>0: prev wk use done)
        {
            const float4* wsrc = (const float4*)(wf + k*WK_ELEMS);
            float4* wdst = (float4*)wk;
            for (int i = tid; i < WK_ELEMS/4; i += 256) wdst[i] = wsrc[i];
        }
        __syncthreads();
        const int ky = k/3, kx = k - ky*3;
        const float* tp = tile + (ly + ky)*TCOLS + (lx + kx);
#pragma unroll 2
        for (int ic = 0; ic < C; ic++) {
            float xv = tp[ic*(TROWS*TCOLS)];
            unsigned long long xx;
            asm("mov.b64 %0, {%1, %1};" : "=l"(xx) : "f"(xv));
            const ulonglong2* wp = (const ulonglong2*)(wk + ic*C);
#pragma unroll
            for (int j = 0; j < 16; j++) {
                ulonglong2 wv = wp[j];
                asm("fma.rn.f32x2 %0, %1, %2, %0;" : "+l"(acc[2*j  ]) : "l"(wv.x), "l"(xx));
                asm("fma.rn.f32x2 %0, %1, %2, %0;" : "+l"(acc[2*j+1]) : "l"(wv.y), "l"(xx));
            }
        }
    }

    const int gy = y0 + ly, gx = x0 + lx;
    if (STORE) {
        float* op = g_f1 + (size_t)b*CHW + gy*W + gx;
#pragma unroll
        for (int p = 0; p < 32; p++) {
            float v0, v1;
            asm("mov.b64 {%0, %1}, %2;" : "=f"(v0), "=f"(v1) : "l"(acc[p]));
            v0 = fmaxf(v0 + bias[2*p    ], 0.f);
            v1 = fmaxf(v1 + bias[2*p + 1], 0.f);
            op[(size_t)(2*p    )*HW] = v0;
            op[(size_t)(2*p + 1)*HW] = v1;
        }
    } else {
        const int warp = tid >> 5;
#pragma unroll
        for (int p = 0; p < 32; p++) {
            float v0, v1;
            asm("mov.b64 {%0, %1}, %2;" : "=f"(v0), "=f"(v1) : "l"(acc[p]));
            v0 = fmaxf(v0 + bias[2*p    ], 0.f);
            v1 = fmaxf(v1 + bias[2*p + 1], 0.f);
#pragma unroll
            for (int s = 16; s; s >>= 1) {
                v0 += __shfl_xor_sync(0xffffffffu, v0, s);
                v1 += __shfl_xor_sync(0xffffffffu, v1, s);
            }
            if (lx == 0) {
                wsum[warp*C + 2*p    ] = v0;
                wsum[warp*C + 2*p + 1] = v1;
            }
        }
        __syncthreads();
        if (tid < C) {
            float s = 0.f;
#pragma unroll
            for (int w = 0; w < 8; w++) s += wsum[w*C + tid];
            int tileIdx = blockIdx.y * NTILES_X + blockIdx.x;
            g_part[((size_t)b*NTILES + tileIdx)*C + tid] = s;
        }
    }
}

// ---------------- tail: pool, MLP, softmax, loss, EMA scatter, output ---
__launch_bounds__(256)
__global__ void tail_kernel(const float* __restrict__ ref_x, const int* __restrict__ ref_types,
                            const float* __restrict__ w1, const float* __restrict__ b1,
                            const float* __restrict__ w2, const float* __restrict__ b2,
                            const float* __restrict__ ref_proj, float* __restrict__ dout) {
    extern __shared__ float sm[];
    float* feat   = sm;              // [32][64]
    float* hidden = feat + 2048;     // [32][128]
    float* logit  = hidden + 4096;   // [32][64] -> becomes type_weights
    float* refnew = logit + 2048;    // [64][64]
    float* lossv  = refnew + 4096;   // [32]
    float* coeff  = lossv + 32;      // [32]
    float* decay  = coeff + 32;      // [64]
    int*   st     = (int*)(decay + 64); // [32]

    const int tid = threadIdx.x;
    if (tid < BS) st[tid] = ref_types[tid];

    // finish pooling: feat[b][c] = mean over HW
    for (int idx = tid; idx < BS*C; idx += 256) {
        int bb = idx >> 6, c = idx & 63;
        float s = 0.f;
        for (int t = 0; t < NTILES; t++) s += g_part[((size_t)bb*NTILES + t)*C + c];
        feat[idx] = s * (1.f/(float)HW);
    }
    __syncthreads();

    // hidden = relu(feat @ w1 + b1)    w1: [64][128]
    for (int idx = tid; idx < BS*HID; idx += 256) {
        int bb = idx >> 7, j = idx & 127;
        float s = b1[j];
        const float* fr = feat + bb*C;
        for (int i = 0; i < C; i++) s += fr[i] * w1[i*HID + j];
        hidden[idx] = fmaxf(s, 0.f);
    }
    __syncthreads();

    // logits = hidden @ w2 + b2       w2: [128][64]
    for (int idx = tid; idx < BS*TT; idx += 256) {
        int bb = idx >> 6, t = idx & 63;
        float s = b2[t];
        const float* hr = hidden + bb*HID;
        for (int j = 0; j < HID; j++) s += hr[j] * w2[j*TT + t];
        logit[idx] = s;
    }
    __syncthreads();

    // per-row softmax (temperature=1) + cross-entropy pieces
    if (tid < BS) {
        float* lr = logit + tid*TT;
        float mx = lr[0];
        for (int t = 1; t < TT; t++) mx = fmaxf(mx, lr[t]);
        float s = 0.f;
        for (int t = 0; t < TT; t++) s += expf(lr[t] - mx);
        lossv[tid] = mx + logf(s) - lr[st[tid]];
        float inv = 1.f / s;
        for (int t = 0; t < TT; t++) lr[t] = expf(lr[t] - mx) * inv;  // in-place -> tw
    }
    // EMA coefficients: decay[t] = 0.99^count_t ; coeff[i] = 0.01*0.99^{#later occ of type_i}
    if (tid < TT) {
        int cnt = 0;
        for (int i = 0; i < BS; i++) cnt += (st[i] == tid);
        float r = 1.f;
        for (int q = 0; q < cnt; q++) r *= 0.99f;
        decay[tid] = r;
    }
    if (tid >= 64 && tid < 96) {
        int i = tid - 64;
        int after = 0;
        for (int j = i + 1; j < BS; j++) after += (st[j] == st[i]);
        float r = 0.01f;
        for (int q = 0; q < after; q++) r *= 0.99f;
        coeff[i] = r;
    }
    __syncthreads();

    // ref_new[t][c] = decay[t]*ref_proj + sum_{i: type_i==t} coeff[i]*ref_x[i]
    for (int idx = tid; idx < TT*C; idx += 256) {
        int t = idx >> 6, c = idx & 63;
        float v = decay[t] * ref_proj[idx];
        for (int i = 0; i < BS; i++)
            if (st[i] == t) v += coeff[i] * ref_x[i*C + c];
        refnew[idx] = v;
        dout[2049 + idx] = v;   // output 3: ref_new [64,64]
    }
    __syncthreads();

    // out[b][c] = ref_x + tw[b] @ ref_new
    for (int idx = tid; idx < BS*C; idx += 256) {
        int bb = idx >> 6, c = idx & 63;
        float s = ref_x[idx];
        const float* twr = logit + bb*TT;
        for (int t = 0; t < TT; t++) s += twr[t] * refnew[t*C + c];
        dout[idx] = s;          // output 1: out [32,64,1,1]
    }
    if (tid == 0) {
        float s = 0.f;
        for (int i = 0; i < BS; i++) s += lossv[i];
        dout[2048] = s * (1.f/(float)BS);   // output 2: loss
    }
}

// ---------------- launch ----------------
extern "C" void kernel_launch(void* const* d_in, const int* in_sizes, int n_in,
                              void* d_out, int out_size) {
    const float* x        = (const float*)d_in[0];
    const float* ref_x    = (const float*)d_in[1];
    const int*   ref_types= (const int*)  d_in[2];
    const float* conv1_w  = (const float*)d_in[3];
    const float* bn1_g    = (const float*)d_in[4];
    const float* bn1_b    = (const float*)d_in[5];
    const float* bn1_m    = (const float*)d_in[6];
    const float* bn1_v    = (const float*)d_in[7];
    const float* conv2_w  = (const float*)d_in[8];
    const float* bn2_g    = (const float*)d_in[9];
    const float* bn2_b    = (const float*)d_in[10];
    const float* bn2_m    = (const float*)d_in[11];
    const float* bn2_v    = (const float*)d_in[12];
    const float* mlp_w1   = (const float*)d_in[13];
    const float* mlp_b1   = (const float*)d_in[14];
    const float* mlp_w2   = (const float*)d_in[15];
    const float* mlp_b2   = (const float*)d_in[16];
    const float* ref_proj = (const float*)d_in[17];
    float* out = (float*)d_out;

    cudaFuncSetAttribute(conv_kernel<1>, cudaFuncAttributeMaxDynamicSharedMemorySize, CONV_SMEM_BYTES);
    cudaFuncSetAttribute(conv_kernel<0>, cudaFuncAttributeMaxDynamicSharedMemorySize, CONV_SMEM_BYTES);
    cudaFuncSetAttribute(tail_kernel,    cudaFuncAttributeMaxDynamicSharedMemorySize, TAIL_SMEM_BYTES);

    prep_kernel<<<144, 256>>>(conv1_w, bn1_g, bn1_b, bn1_m, bn1_v,
                              conv2_w, bn2_g, bn2_b, bn2_m, bn2_v);

    dim3 cgrid(NTILES_X, NTILES_Y, BS);
    conv_kernel<1><<<cgrid, 256, CONV_SMEM_BYTES>>>(x);
    conv_kernel<0><<<cgrid, 256, CONV_SMEM_BYTES>>>(x);

    tail_kernel<<<1, 256, TAIL_SMEM_BYTES>>>(ref_x, ref_types, mlp_w1, mlp_b1,
                                             mlp_w2, mlp_b2, ref_proj, out);
}

// round 2
// speedup vs baseline: 1.7099x; 1.7099x over previous
#include <cuda_runtime.h>
#include <cuda_bf16.h>
#include <cstdint>

// ---------------- problem constants ----------------
#define BS   32
#define C    64
#define H    96
#define W    96
#define HW   (H*W)            // 9216
#define CHW  (C*HW)           // 589824
#define TT   64               // num types
#define HID  128              // 2c
#define EPS  1e-5f

// conv tiling
#define TILE_X 32
#define TILE_Y 8
#define TROWS  (TILE_Y+2)     // 10
#define TCOLS  35             // 32+2 halo, padded to 35 for conflict-free LDS
#define TILE_ELEMS (C*TROWS*TCOLS)   // 22400
#define WK_ELEMS   (C*C)             // 4096
#define WSUM_ELEMS (8*16)            // 128
#define CONV_SMEM_FLOATS (TILE_ELEMS + WK_ELEMS + WSUM_ELEMS)
#define CONV_SMEM_BYTES  (CONV_SMEM_FLOATS*4)   // 106112

#define NTILES_X (W/TILE_X)   // 3
#define NTILES_Y (H/TILE_Y)   // 12
#define NTILES   (NTILES_X*NTILES_Y) // 36

// tail smem: w1s(8192) + w2s(8192) + feat(2048) + hidden(4096) + logit(2048)
//            + refnew(4096) + lossv/coeff/decay/st (160)
#define TAIL_SMEM_FLOATS (8192+8192+2048+4096+2048+4096+160)
#define TAIL_SMEM_BYTES  (TAIL_SMEM_FLOATS*4)

// ---------------- device scratch (static: no runtime allocs allowed) ----
__device__ float g_f1[BS*CHW];                 // intermediate feature map (~75.5MB)
__device__ float g_wf1[9*C*C];                 // folded conv1 weights [k][ic][oc]
__device__ float g_wf2[9*C*C];
__device__ float g_bias1[C];
__device__ float g_bias2[C];
__device__ float g_part[BS*NTILES*C];          // pooled partial sums per tile

// ---------------- prep: fold BN into weights, layout [k][ic][oc] --------
__global__ void prep_kernel(const float* __restrict__ w1, const float* __restrict__ g1,
                            const float* __restrict__ b1, const float* __restrict__ m1,
                            const float* __restrict__ v1,
                            const float* __restrict__ w2, const float* __restrict__ g2,
                            const float* __restrict__ b2, const float* __restrict__ m2,
                            const float* __restrict__ v2) {
    int idx = blockIdx.x*256 + threadIdx.x;
    if (idx < 9*C*C) {
        int oc = idx & 63;
        int ic = (idx >> 6) & 63;
        int k  = idx >> 12;
        float s1 = g1[oc] * rsqrtf(v1[oc] + EPS);
        float s2 = g2[oc] * rsqrtf(v2[oc] + EPS);
        // source layout: w[oc][ic][ky][kx]
        g_wf1[idx] = w1[(oc*C + ic)*9 + k] * s1;
        g_wf2[idx] = w2[(oc*C + ic)*9 + k] * s2;
    }
    if (idx < C) {
        g_bias1[idx] = b1[idx] - m1[idx]*g1[idx]*rsqrtf(v1[idx] + EPS);
        g_bias2[idx] = b2[idx] - m2[idx]*g2[idx]*rsqrtf(v2[idx] + EPS);
    }
}

// ---------------- direct conv, 16 oc x 4 px per thread, f32x2 accs ------
// STORE=1: read param input, write relu result to g_f1
// STORE=0: read g_f1, reduce relu result spatially into g_part
template<int STORE>
__launch_bounds__(256, 2)
__global__ void conv_kernel(const float* __restrict__ xin) {
    extern __shared__ float smem[];
    float* tile = smem;                       // [C][TROWS][TCOLS]
    float* wk   = smem + TILE_ELEMS;          // [ic][oc] for current k
    float* wsum = wk + WK_ELEMS;              // [8 warps][16]

    const int tid = threadIdx.x;
    const int oc_grp = tid >> 6;              // 0..3
    const int oc0 = oc_grp << 4;              // 16 oc per thread
    const int p = tid & 63;
    const int row = p >> 3;                   // 0..7
    const int colbase = (p & 7) << 2;         // 0,4,...,28  (4 px per thread)

    const int x0 = blockIdx.x * TILE_X, y0 = blockIdx.y * TILE_Y;
    const int b  = blockIdx.z;

    const float* in   = STORE ? xin : g_f1;
    const float* wf   = STORE ? g_wf1 : g_wf2;
    const float* bias = STORE ? g_bias1 : g_bias2;
    const float* inb  = in + (size_t)b * CHW;

    // load input tile with halo (zero pad at borders)
    for (int idx = tid; idx < TILE_ELEMS; idx += 256) {
        int ch  = idx / (TROWS*TCOLS);
        int rem = idx - ch*(TROWS*TCOLS);
        int r   = rem / TCOLS;
        int col = rem - r*TCOLS;
        int gy = y0 + r - 1, gx = x0 + col - 1;
        float v = 0.f;
        if (gy >= 0 && gy < H && gx >= 0 && gx < W && col < 34)
            v = inb[ch*HW + gy*W + gx];
        tile[idx] = v;
    }

    unsigned long long acc[8][4];   // acc[j][q]: oc pair (oc0+2j, oc0+2j+1), pixel q
#pragma unroll
    for (int j = 0; j < 8; j++)
#pragma unroll
        for (int q = 0; q < 4; q++) acc[j][q] = 0ull;

    for (int k = 0; k < 9; k++) {
        __syncthreads();   // (k=0: tile ready; k>0: prev wk use done)
        {
            const float4* wsrc = (const float4*)(wf + k*WK_ELEMS);
            float4* wdst = (float4*)wk;
#pragma unroll
            for (int i = 0; i < 4; i++) wdst[tid + 256*i] = wsrc[tid + 256*i];
        }
        __syncthreads();
        const int ky = k/3, kx = k - ky*3;
        const float* xbase = tile + (row + ky)*TCOLS + (colbase + kx);
#pragma unroll 2
        for (int ic = 0; ic < C; ic++) {
            const float* xp = xbase + ic*(TROWS*TCOLS);
            unsigned long long xx[4];
#pragma unroll
            for (int q = 0; q < 4; q++) {
                float xv = xp[q];
                asm("mov.b64 %0, {%1, %1};" : "=l"(xx[q]) : "f"(xv));
            }
            const ulonglong2* wp = (const ulonglong2*)(wk + ic*C + oc0);
            ulonglong2 w01 = wp[0], w23 = wp[1], w45 = wp[2], w67 = wp[3];
            unsigned long long wv[8] = {w01.x, w01.y, w23.x, w23.y,
                                        w45.x, w45.y, w67.x, w67.y};
#pragma unroll
            for (int j = 0; j < 8; j++)
#pragma unroll
                for (int q = 0; q < 4; q++)
                    asm("fma.rn.f32x2 %0, %1, %2, %0;"
                        : "+l"(acc[j][q]) : "l"(wv[j]), "l"(xx[q]));
        }
    }

    const int gy = y0 + row;
    const int gx = x0 + colbase;
    if (STORE) {
        float* op = g_f1 + (size_t)b*CHW + gy*W + gx;
#pragma unroll
        for (int j = 0; j < 8; j++) {
            float lo[4], hi[4];
#pragma unroll
            for (int q = 0; q < 4; q++)
                asm("mov.b64 {%0, %1}, %2;" : "=f"(lo[q]), "=f"(hi[q]) : "l"(acc[j][q]));
            float blo = bias[oc0 + 2*j], bhi = bias[oc0 + 2*j + 1];
            float4 vlo, vhi;
            vlo.x = fmaxf(lo[0]+blo, 0.f); vlo.y = fmaxf(lo[1]+blo, 0.f);
            vlo.z = fmaxf(lo[2]+blo, 0.f); vlo.w = fmaxf(lo[3]+blo, 0.f);
            vhi.x = fmaxf(hi[0]+bhi, 0.f); vhi.y = fmaxf(hi[1]+bhi, 0.f);
            vhi.z = fmaxf(hi[2]+bhi, 0.f); vhi.w = fmaxf(hi[3]+bhi, 0.f);
            *(float4*)(op + (size_t)(oc0 + 2*j    )*HW) = vlo;
            *(float4*)(op + (size_t)(oc0 + 2*j + 1)*HW) = vhi;
        }
    } else {
        const int warp = tid >> 5;
        const int lane = tid & 31;
#pragma unroll
        for (int j = 0; j < 8; j++) {
            float lo[4], hi[4];
#pragma unroll
            for (int q = 0; q < 4; q++)
                asm("mov.b64 {%0, %1}, %2;" : "=f"(lo[q]), "=f"(hi[q]) : "l"(acc[j][q]));
            float blo = bias[oc0 + 2*j], bhi = bias[oc0 + 2*j + 1];
            float slo = fmaxf(lo[0]+blo,0.f) + fmaxf(lo[1]+blo,0.f)
                      + fmaxf(lo[2]+blo,0.f) + fmaxf(lo[3]+blo,0.f);
            float shi = fmaxf(hi[0]+bhi,0.f) + fmaxf(hi[1]+bhi,0.f)
                      + fmaxf(hi[2]+bhi,0.f) + fmaxf(hi[3]+bhi,0.f);
#pragma unroll
            for (int s = 16; s; s >>= 1) {
                slo += __shfl_xor_sync(0xffffffffu, slo, s);
                shi += __shfl_xor_sync(0xffffffffu, shi, s);
            }
            if (lane == 0) {
                wsum[warp*16 + 2*j    ] = slo;
                wsum[warp*16 + 2*j + 1] = shi;
            }
        }
        __syncthreads();
        if (tid < C) {
            int g = tid >> 4, r = tid & 15;
            float s = wsum[(2*g)*16 + r] + wsum[(2*g+1)*16 + r];
            int tileIdx = blockIdx.y * NTILES_X + blockIdx.x;
            g_part[((size_t)b*NTILES + tileIdx)*C + tid] = s;
        }
    }
}

// ---------------- tail: pool, MLP, softmax, loss, EMA scatter, output ---
__launch_bounds__(256)
__global__ void tail_kernel(const float* __restrict__ ref_x, const int* __restrict__ ref_types,
                            const float* __restrict__ w1, const float* __restrict__ b1,
                            const float* __restrict__ w2, const float* __restrict__ b2,
                            const float* __restrict__ ref_proj, float* __restrict__ dout) {
    extern __shared__ float sm[];
    float* w1s    = sm;              // [64][128]
    float* w2s    = w1s + 8192;      // [128][64]
    float* feat   = w2s + 8192;      // [32][64]
    float* hidden = feat + 2048;     // [32][128]
    float* logit  = hidden + 4096;   // [32][64] -> becomes type_weights
    float* refnew = logit + 2048;    // [64][64]
    float* lossv  = refnew + 4096;   // [32]
    float* coeff  = lossv + 32;      // [32]
    float* decay  = coeff + 32;      // [64]
    int*   st     = (int*)(decay + 64); // [32]

    const int tid = threadIdx.x;
    if (tid < BS) st[tid] = ref_types[tid];

    // stage MLP weights (coalesced) + finish pooling in parallel
    for (int i = tid; i < 8192; i += 256) { w1s[i] = w1[i]; w2s[i] = w2[i]; }
    for (int idx = tid; idx < BS*C; idx += 256) {
        int bb = idx >> 6, c = idx & 63;
        float s = 0.f;
#pragma unroll 6
        for (int t = 0; t < NTILES; t++) s += g_part[((size_t)bb*NTILES + t)*C + c];
        feat[idx] = s * (1.f/(float)HW);
    }
    __syncthreads();

    // hidden = relu(feat @ w1 + b1)    w1: [64][128]
    for (int idx = tid; idx < BS*HID; idx += 256) {
        int bb = idx >> 7, j = idx & 127;
        float s = b1[j];
        const float* fr = feat + bb*C;
#pragma unroll 8
        for (int i = 0; i < C; i++) s += fr[i] * w1s[i*HID + j];
        hidden[idx] = fmaxf(s, 0.f);
    }
    __syncthreads();

    // logits = hidden @ w2 + b2       w2: [128][64]
    for (int idx = tid; idx < BS*TT; idx += 256) {
        int bb = idx >> 6, t = idx & 63;
        float s = b2[t];
        const float* hr = hidden + bb*HID;
#pragma unroll 8
        for (int j = 0; j < HID; j++) s += hr[j] * w2s[j*TT + t];
        logit[idx] = s;
    }
    __syncthreads();

    // per-row softmax (temperature=1) + cross-entropy pieces
    if (tid < BS) {
        float* lr = logit + tid*TT;
        float mx = lr[0];
        for (int t = 1; t < TT; t++) mx = fmaxf(mx, lr[t]);
        float s = 0.f;
        for (int t = 0; t < TT; t++) s += expf(lr[t] - mx);
        lossv[tid] = mx + logf(s) - lr[st[tid]];
        float inv = 1.f / s;
        for (int t = 0; t < TT; t++) lr[t] = expf(lr[t] - mx) * inv;  // in-place -> tw
    }
    // EMA coefficients: decay[t] = 0.99^count_t ; coeff[i] = 0.01*0.99^{#later occ of type_i}
    if (tid < TT) {
        int cnt = 0;
        for (int i = 0; i < BS; i++) cnt += (st[i] == tid);
        float r = 1.f;
        for (int q = 0; q < cnt; q++) r *= 0.99f;
        decay[tid] = r;
    }
    if (tid >= 64 && tid < 96) {
        int i = tid - 64;
        int after = 0;
        for (int j = i + 1; j < BS; j++) after += (st[j] == st[i]);
        float r = 0.01f;
        for (int q = 0; q < after; q++) r *= 0.99f;
        coeff[i] = r;
    }
    __syncthreads();

    // ref_new[t][c] = decay[t]*ref_proj + sum_{i: type_i==t} coeff[i]*ref_x[i]
    for (int idx = tid; idx < TT*C; idx += 256) {
        int t = idx >> 6, c = idx & 63;
        float v = decay[t] * ref_proj[idx];
        for (int i = 0; i < BS; i++)
            if (st[i] == t) v += coeff[i] * ref_x[i*C + c];
        refnew[idx] = v;
        dout[2049 + idx] = v;   // output 3: ref_new [64,64]
    }
    __syncthreads();

    // out[b][c] = ref_x + tw[b] @ ref_new
    for (int idx = tid; idx < BS*C; idx += 256) {
        int bb = idx >> 6, c = idx & 63;
        float s = ref_x[idx];
        const float* twr = logit + bb*TT;
#pragma unroll 8
        for (int t = 0; t < TT; t++) s += twr[t] * refnew[t*C + c];
        dout[idx] = s;          // output 1: out [32,64,1,1]
    }
    if (tid == 0) {
        float s = 0.f;
        for (int i = 0; i < BS; i++) s += lossv[i];
        dout[2048] = s * (1.f/(float)BS);   // output 2: loss
    }
}

// ---------------- launch ----------------
extern "C" void kernel_launch(void* const* d_in, const int* in_sizes, int n_in,
                              void* d_out, int out_size) {
    const float* x        = (const float*)d_in[0];
    const float* ref_x    = (const float*)d_in[1];
    const int*   ref_types= (const int*)  d_in[2];
    const float* conv1_w  = (const float*)d_in[3];
    const float* bn1_g    = (const float*)d_in[4];
    const float* bn1_b    = (const float*)d_in[5];
    const float* bn1_m    = (const float*)d_in[6];
    const float* bn1_v    = (const float*)d_in[7];
    const float* conv2_w  = (const float*)d_in[8];
    const float* bn2_g    = (const float*)d_in[9];
    const float* bn2_b    = (const float*)d_in[10];
    const float* bn2_m    = (const float*)d_in[11];
    const float* bn2_v    = (const float*)d_in[12];
    const float* mlp_w1   = (const float*)d_in[13];
    const float* mlp_b1   = (const float*)d_in[14];
    const float* mlp_w2   = (const float*)d_in[15];
    const float* mlp_b2   = (const float*)d_in[16];
    const float* ref_proj = (const float*)d_in[17];
    float* out = (float*)d_out;

    cudaFuncSetAttribute(conv_kernel<1>, cudaFuncAttributeMaxDynamicSharedMemorySize, CONV_SMEM_BYTES);
    cudaFuncSetAttribute(conv_kernel<0>, cudaFuncAttributeMaxDynamicSharedMemorySize, CONV_SMEM_BYTES);
    cudaFuncSetAttribute(tail_kernel,    cudaFuncAttributeMaxDynamicSharedMemorySize, TAIL_SMEM_BYTES);

    prep_kernel<<<144, 256>>>(conv1_w, bn1_g, bn1_b, bn1_m, bn1_v,
                              conv2_w, bn2_g, bn2_b, bn2_m, bn2_v);

    dim3 cgrid(NTILES_X, NTILES_Y, BS);
    conv_kernel<1><<<cgrid, 256, CONV_SMEM_BYTES>>>(x);
    conv_kernel<0><<<cgrid, 256, CONV_SMEM_BYTES>>>(x);

    tail_kernel<<<1, 256, TAIL_SMEM_BYTES>>>(ref_x, ref_types, mlp_w1, mlp_b1,
                                             mlp_w2, mlp_b2, ref_proj, out);
}